// round 15
// baseline (speedup 1.0000x reference)
#include <cuda_runtime.h>

// IDGNN restructured (math validated R2-R14, rel_err ~2e-7):
//   p_i = MLP_{0,i}(x);  u = x + A*p0;  d = p1 - p0
//   Un_i = u*W1e[1,i]; Dt_i = d*W1e[1,i]   (W1e[k] = w1[k]+w1[k+128], inline fold)
//   S_t = sum_{n in N(t)} relu(Un0[n] + Dt0[t] + b1[1,0])
//   out[t] = u_t + self_t*d_t + S_t*w2[1,0] + deg_t*b2[1,0]
//            + self_t*(corr1_t - corr0_t), corr_i = relu(Un_i+Dt_i+b1[1,i]).w2[1,i]+b2[1,i]
// R15: 3 kernels -> 2. 256 threads/block (8-way split-K halves per-warp chains).
// k_udout fuses k_ud and k_out with ONE hierarchical grid barrier (128
// co-resident blocks). g_adj restored in phase B; barrier gen monotonic.

#define NN 256
#define DD 128

// ---- device scratch (zero-init at load; g_adj restored by k_udout B) ----
__device__ unsigned g_adj[NN * 8];
__device__ __align__(16) float g_p0[NN * DD];
__device__ __align__(16) float g_p1[NN * DD];
__device__ __align__(16) float g_u [NN * DD];
__device__ __align__(16) float g_d [NN * DD];
__device__ __align__(16) float g_UD[4][NN * DD];   // 0:Un0 1:Dt0 2:Un1 3:Dt1
__device__ __align__(16) float g_corr[2][NN * DD];
__device__ unsigned g_leaf[16 * 64];   // 256B stride -> distinct L2 slices
__device__ unsigned g_root;
__device__ unsigned g_gen;

__device__ __forceinline__ float4 f4add(float4 a, float4 b) {
    return make_float4(a.x + b.x, a.y + b.y, a.z + b.z, a.w + b.w);
}
__device__ __forceinline__ float4 f4fma(float s, float4 w, float4 a) {
    return make_float4(fmaf(s, w.x, a.x), fmaf(s, w.y, a.y),
                       fmaf(s, w.z, a.z), fmaf(s, w.w, a.w));
}
__device__ __forceinline__ float4 f4relu(float4 a) {
    return make_float4(fmaxf(a.x, 0.f), fmaxf(a.y, 0.f),
                       fmaxf(a.z, 0.f), fmaxf(a.w, 0.f));
}
__device__ __forceinline__ unsigned ldcg_u32(const unsigned* p) {
    unsigned v;
    asm volatile("ld.global.cg.u32 %0, [%1];" : "=r"(v) : "l"(p));
    return v;
}

// Hierarchical grid barrier: 16 leaves x 8 arrivals + 16-arrival root.
// Poll is a plain L2 load; counters self-reset; g_gen monotonic across replays.
__device__ __forceinline__ void grid_sync(unsigned target, int bid) {
    __syncthreads();
    if (threadIdx.x == 0) {
        __threadfence();
        unsigned* leaf = &g_leaf[(bid & 15) * 64];
        unsigned a = atomicAdd(leaf, 1u);
        if (a == 7u) {
            atomicExch(leaf, 0u);
            unsigned rr = atomicAdd(&g_root, 1u);
            if (rr == 15u) {
                atomicExch(&g_root, 0u);
                __threadfence();
                atomicExch(&g_gen, target);
            }
        }
        while (ldcg_u32(&g_gen) != target) __nanosleep(32);
        __threadfence();
    }
    __syncthreads();
}

// Expand g_adj[row] bitmask into nbr[] (full warp). Returns count.
__device__ __forceinline__ int build_list(int row, int* nbr) {
    int lane = threadIdx.x & 31;
    unsigned word = (lane < 8) ? g_adj[row * 8 + lane] : 0u;
    int pc = __popc(word);
    int inc = pc;
#pragma unroll
    for (int off = 1; off < 8; off <<= 1) {
        int v = __shfl_up_sync(0xffffffffu, inc, off);
        if (lane >= off) inc += v;
    }
    int base = inc - pc;
    if (lane < 8) {
        unsigned bits = word; int o = base;
        while (bits) { int b = __ffs(bits) - 1; bits &= bits - 1; nbr[o++] = lane * 32 + b; }
    }
    return __shfl_sync(0xffffffffu, inc, 7);
}

// ---------------------------------------------------------------------------
// K1: blocks [0,128): p_i = (relu(x*W1e[0,i]+b1[0,i]))*w2[0,i]+b2[0,i]
//     4 rows/block, 8-way split-K float4, inline fold.
//     blocks [128,144): edge scatter into g_adj (first consumed by k_udout).
// ---------------------------------------------------------------------------
__global__ void __launch_bounds__(256, 1)
k_p(const int* __restrict__ ei32, int E,
    const float4* __restrict__ x4, const float4* __restrict__ w14,
    const float* __restrict__ b1, const float4* __restrict__ w24,
    const float* __restrict__ b2) {
    int tid = threadIdx.x, lane = tid & 31, w = tid >> 5;
    if (blockIdx.x >= 128) {                  // edge scatter
        // dtype sniff: int64 node ids (<256, nonneg) => odd int32 words zero
        int probe = (2 * tid + 1 < 2 * E) ? ei32[2 * tid + 1] : 0;
        int is64 = __syncthreads_and(probe == 0);
        for (int e = (blockIdx.x - 128) * 256 + tid; e < E; e += 16 * 256) {
            int a, b;
            if (is64) { a = ei32[2 * e]; b = ei32[2 * (E + e)]; }
            else      { a = ei32[e];     b = ei32[E + e]; }
            a &= 255; b &= 255;
            atomicOr(&g_adj[a * 8 + (b >> 5)], 1u << (b & 31));
            atomicOr(&g_adj[b * 8 + (a >> 5)], 1u << (a & 31));
        }
        return;
    }
    int i = blockIdx.x >> 6, row0 = (blockIdx.x & 63) * 4;
    int kb = w * 16;
    __shared__ __align__(16) float S[4][DD];
    __shared__ __align__(16) float H[4][DD];
    __shared__ __align__(16) float red[8][4][DD];

    if (tid < 128) ((float4*)S[tid >> 5])[lane] = x4[(row0 + (tid >> 5)) * 32 + lane];
    __syncthreads();

    {   // L1 GEMM with inline fold
        const float4* W = w14 + i * 8192;     // w1[0,i]
        float4 acc[4] = {};
#pragma unroll
        for (int kk = 0; kk < 16; kk++) {
            int k = kb + kk;
            float4 we = f4add(W[k * 32 + lane], W[(k + 128) * 32 + lane]);
#pragma unroll
            for (int r = 0; r < 4; r++) acc[r] = f4fma(S[r][k], we, acc[r]);
        }
#pragma unroll
        for (int r = 0; r < 4; r++) ((float4*)red[w][r])[lane] = acc[r];
    }
    __syncthreads();
#pragma unroll
    for (int v = 0; v < 2; v++) {             // H = relu(sum + b1[0,i])
        int idx = tid + 256 * v, r = idx >> 7, c = idx & 127;
        float s = b1[i * DD + c];
#pragma unroll
        for (int ww = 0; ww < 8; ww++) s += red[ww][r][c];
        H[r][c] = fmaxf(s, 0.f);
    }
    __syncthreads();
    {   // L2 GEMM
        const float4* W2 = w24 + i * 4096;    // w2[0,i]
        float4 acc[4] = {};
#pragma unroll
        for (int kk = 0; kk < 16; kk++) {
            int k = kb + kk;
            float4 wv = W2[k * 32 + lane];
#pragma unroll
            for (int r = 0; r < 4; r++) acc[r] = f4fma(H[r][k], wv, acc[r]);
        }
#pragma unroll
        for (int r = 0; r < 4; r++) ((float4*)red[w][r])[lane] = acc[r];
    }
    __syncthreads();
    {
        float* dst = i ? g_p1 : g_p0;
#pragma unroll
        for (int v = 0; v < 2; v++) {
            int idx = tid + 256 * v, r = idx >> 7, c = idx & 127;
            float s = b2[i * DD + c];
#pragma unroll
            for (int ww = 0; ww < 8; ww++) s += red[ww][r][c];
            dst[(row0 + r) * DD + c] = s;
        }
    }
}

// ---------------------------------------------------------------------------
// K2 phase A (= old k_ud + corr): 128 blocks x 256 thr; i = bid>>6, 4 rows.
//    phase B (= old k_out) after ONE grid barrier: rows 2*bid, 2*bid+1.
// ---------------------------------------------------------------------------
__global__ void __launch_bounds__(256, 1)
k_udout(const float4* __restrict__ x4, const float4* __restrict__ w14,
        const float* __restrict__ b1, const float4* __restrict__ w24,
        const float* __restrict__ b2, float* __restrict__ out) {
    int tid = threadIdx.x, lane = tid & 31, w = tid >> 5, bid = blockIdx.x;
    int i = bid >> 6, row0 = (bid & 63) * 4;
    int kb = w * 16;
    __shared__ __align__(16) float U[4][DD];          // U / H / Ssum
    __shared__ __align__(16) float D[4][DD];
    __shared__ __align__(16) float red[8][8][DD];     // 32KB partials
    __shared__ int nbr[4][NN];
    __shared__ int cnts[4];
    __shared__ unsigned genS;

    if (tid == 0) genS = ldcg_u32(&g_gen);

    // ---- lists (warps 0-3) and d (warps 4-7) ----
    if (w < 4) {
        int cn = build_list(row0 + w, nbr[w]);
        if (lane == 0) cnts[w] = cn;
    } else {
        int row = row0 + (w - 4);
        float4 p1v = ((const float4*)g_p1)[row * 32 + lane];
        float4 p0v = ((const float4*)g_p0)[row * 32 + lane];
        float4 dv = make_float4(p1v.x - p0v.x, p1v.y - p0v.y,
                                p1v.z - p0v.z, p1v.w - p0v.w);
        ((float4*)D[w - 4])[lane] = dv;
        if (i == 0) ((float4*)g_d)[row * 32 + lane] = dv;
    }
    __syncthreads();
    const unsigned gen0 = genS;
    {   // u-gather: warp (r = w&3, half = w>>2) splits list mod 2
        int r = w & 3, half = w >> 2;
        const float4* p04 = (const float4*)g_p0;
        int cn = cnts[r];
        float4 s0 = {}, s1 = {};
        int j = half;
        for (; j + 2 < cn; j += 4) {
            s0 = f4add(s0, p04[nbr[r][j]     * 32 + lane]);
            s1 = f4add(s1, p04[nbr[r][j + 2] * 32 + lane]);
        }
        if (j < cn) s0 = f4add(s0, p04[nbr[r][j] * 32 + lane]);
        ((float4*)red[w][0])[lane] = f4add(s0, s1);   // w = half*4 + r
    }
    __syncthreads();
#pragma unroll
    for (int v = 0; v < 2; v++) {             // U = x + partials
        int idx = tid + 256 * v, r = idx >> 7, c = idx & 127;
        float uv = ((const float*)x4)[(row0 + r) * DD + c]
                 + red[r][0][c] + red[4 + r][0][c];
        U[r][c] = uv;
        if (i == 0) g_u[(row0 + r) * DD + c] = uv;
    }
    __syncthreads();
    {   // L1 GEMM with inline fold: w1[1,i]; U and D share each weight
        const float4* W = w14 + (2 + i) * 8192;
        float4 aU[4] = {}, aD[4] = {};
#pragma unroll
        for (int kk = 0; kk < 16; kk++) {
            int k = kb + kk;
            float4 we = f4add(W[k * 32 + lane], W[(k + 128) * 32 + lane]);
#pragma unroll
            for (int r = 0; r < 4; r++) {
                aU[r] = f4fma(U[r][k], we, aU[r]);
                aD[r] = f4fma(D[r][k], we, aD[r]);
            }
        }
#pragma unroll
        for (int r = 0; r < 4; r++) {
            ((float4*)red[w][r])[lane]     = aU[r];
            ((float4*)red[w][4 + r])[lane] = aD[r];
        }
    }
    __syncthreads();
    {   // reduce 1024 vals; each thread sees Un and Dt for rows t, t+2
        float unv[2], dtv[2];
#pragma unroll
        for (int v = 0; v < 4; v++) {
            int idx = tid + 256 * v;
            int isD = idx >> 9, r = (idx >> 7) & 3, c = idx & 127;
            float s = 0.f;
#pragma unroll
            for (int ww = 0; ww < 8; ww++) s += red[ww][isD * 4 + r][c];
            g_UD[2 * i + isD][(row0 + r) * DD + c] = s;
            int slot = (v & 1);               // v0,v1: Un rows t,t+2; v2,v3: Dt
            if (isD) dtv[slot] = s; else unv[slot] = s;
        }
        __syncthreads();
        // H_i = relu(Un+Dt+b1[1,i]) for rows t=tid>>7 and t+2 (reuse U)
        int t = tid >> 7, c = tid & 127;
        float b1v = b1[(2 + i) * DD + c];
        U[t][c]     = fmaxf(unv[0] + dtv[0] + b1v, 0.f);
        U[t + 2][c] = fmaxf(unv[1] + dtv[1] + b1v, 0.f);
    }
    __syncthreads();
    {   // corr GEMM vs w2[1,i]
        const float4* W2 = w24 + (2 + i) * 4096;
        float4 ac[4] = {};
#pragma unroll
        for (int kk = 0; kk < 16; kk++) {
            int k = kb + kk;
            float4 wv = W2[k * 32 + lane];
#pragma unroll
            for (int r = 0; r < 4; r++) ac[r] = f4fma(U[r][k], wv, ac[r]);
        }
#pragma unroll
        for (int r = 0; r < 4; r++) ((float4*)red[w][r])[lane] = ac[r];
    }
    __syncthreads();
#pragma unroll
    for (int v = 0; v < 2; v++) {
        int idx = tid + 256 * v, r = idx >> 7, c = idx & 127;
        float s = b2[(2 + i) * DD + c];
#pragma unroll
        for (int ww = 0; ww < 8; ww++) s += red[ww][r][c];
        g_corr[i][(row0 + r) * DD + c] = s;
    }

    grid_sync(gen0 + 1, bid);

    // =================== phase B: rows t0 = 2*bid, t0+1 =====================
    int t0 = bid * 2;
    if (w < 2) {
        int cn = build_list(t0 + w, nbr[w]);
        if (lane == 0) cnts[w] = cn;
    }
    __syncthreads();
    {   // relu-gather: warp (r = w&1, q = w>>1) takes positions q, q+4, ...
        int r = w & 1, q = w >> 1;
        int row = t0 + r;
        const float4* UD0 = (const float4*)g_UD[0];
        float4 pre = f4add(((const float4*)g_UD[1])[row * 32 + lane],
                           ((const float4*)(b1 + 2 * DD))[lane]);
        int cn = cnts[r];
        float4 s0 = {}, s1 = {};
        int j = q;
        for (; j + 4 < cn; j += 8) {
            s0 = f4add(s0, f4relu(f4add(UD0[nbr[r][j]     * 32 + lane], pre)));
            s1 = f4add(s1, f4relu(f4add(UD0[nbr[r][j + 4] * 32 + lane], pre)));
        }
        if (j < cn) s0 = f4add(s0, f4relu(f4add(UD0[nbr[r][j] * 32 + lane], pre)));
        ((float4*)red[w][0])[lane] = f4add(s0, s1);   // w = q*2 + r
    }
    __syncthreads();
    if (tid < 256) {                          // Ssum into U[0..1]
        int r = tid >> 7, c = tid & 127;
        U[r][c] = red[r][0][c] + red[2 + r][0][c]
                + red[4 + r][0][c] + red[6 + r][0][c];
    }
    __syncthreads();
    {   // final matvec vs w2[1,0]: warp (r = w&1, q = w>>1), k in [q*32,+32)
        int r = w & 1, q = w >> 1;
        float4 acc = {};
#pragma unroll
        for (int kk = 0; kk < 32; kk++) {
            int k = q * 32 + kk;
            float4 wv = w24[8192 + k * 32 + lane];
            acc = f4fma(U[r][k], wv, acc);
        }
        ((float4*)red[w][0])[lane] = acc;
    }
    __syncthreads();
    {   // epilogue: thread (r = tid>>7, c)
        int r = tid >> 7, c = tid & 127;
        int t = t0 + r;
        unsigned diag = g_adj[t * 8 + (t >> 5)];
        float sf = (float)((diag >> (t & 31)) & 1);
        float a2 = red[r][0][c] + red[2 + r][0][c]
                 + red[4 + r][0][c] + red[6 + r][0][c];
        float res = g_u[t * DD + c] + sf * g_d[t * DD + c]
                  + a2 + (float)cnts[r] * b2[2 * DD + c]
                  + sf * (g_corr[1][t * DD + c] - g_corr[0][t * DD + c]);
        out[t * DD + c] = res;
    }
    // restore adjacency rows t0, t0+1 for the next graph replay
    __syncthreads();
    if (tid < 16) g_adj[t0 * 8 + tid] = 0u;
}

extern "C" void kernel_launch(void* const* d_in, const int* in_sizes, int n_in,
                              void* d_out, int out_size) {
    const float* x  = (const float*)d_in[0];
    const float* w1 = (const float*)d_in[1];
    const float* b1 = (const float*)d_in[2];
    const float* w2 = (const float*)d_in[3];
    const float* b2 = (const float*)d_in[4];
    const int*   ei = (const int*)d_in[5];   // dtype sniffed on device
    int E = in_sizes[5] / 2;
    float* out = (float*)d_out;

    k_p    <<<144, 256>>>(ei, E, (const float4*)x, (const float4*)w1,
                          b1, (const float4*)w2, b2);
    k_udout<<<128, 256>>>((const float4*)x, (const float4*)w1,
                          b1, (const float4*)w2, b2, out);
}

// round 16
// speedup vs baseline: 1.1281x; 1.1281x over previous
#include <cuda_runtime.h>

// IDGNN restructured (math validated R2-R15, rel_err ~2e-7):
//   p_i = MLP_{0,i}(x);  u = x + A*p0;  d = p1 - p0
//   Un_i = u*W1e[1,i]; Dt_i = d*W1e[1,i]   (W1e[k] = w1[k]+w1[k+128], inline fold)
//   S_t = sum_{n in N(t)} relu(Un0[n] + Dt0[t] + b1[1,0])
//   out[t] = u_t + self_t*d_t + S_t*w2[1,0] + deg_t*b2[1,0]
//            + self_t*(corr1_t - corr0_t), corr_i = relu(Un_i+Dt_i+b1[1,i]).w2[1,i]+b2[1,i]
// R16 = best of R14+R15: 3 kernels (NO grid barrier — launches beat barriers),
// all 256-thread 8-way split-K blocks (measured: k_p 7.6 -> ~5.1 us).

#define NN 256
#define DD 128

// ---- device scratch (zero-init at load; g_adj restored by k_out) ----
__device__ unsigned g_adj[NN * 8];
__device__ __align__(16) float g_p0[NN * DD];
__device__ __align__(16) float g_p1[NN * DD];
__device__ __align__(16) float g_u [NN * DD];
__device__ __align__(16) float g_d [NN * DD];
__device__ __align__(16) float g_UD[4][NN * DD];   // 0:Un0 1:Dt0 2:Un1 3:Dt1
__device__ __align__(16) float g_corr[2][NN * DD];

__device__ __forceinline__ float4 f4add(float4 a, float4 b) {
    return make_float4(a.x + b.x, a.y + b.y, a.z + b.z, a.w + b.w);
}
__device__ __forceinline__ float4 f4fma(float s, float4 w, float4 a) {
    return make_float4(fmaf(s, w.x, a.x), fmaf(s, w.y, a.y),
                       fmaf(s, w.z, a.z), fmaf(s, w.w, a.w));
}
__device__ __forceinline__ float4 f4relu(float4 a) {
    return make_float4(fmaxf(a.x, 0.f), fmaxf(a.y, 0.f),
                       fmaxf(a.z, 0.f), fmaxf(a.w, 0.f));
}

// Expand g_adj[row] bitmask into nbr[] (full warp). Returns count.
__device__ __forceinline__ int build_list(int row, int* nbr) {
    int lane = threadIdx.x & 31;
    unsigned word = (lane < 8) ? g_adj[row * 8 + lane] : 0u;
    int pc = __popc(word);
    int inc = pc;
#pragma unroll
    for (int off = 1; off < 8; off <<= 1) {
        int v = __shfl_up_sync(0xffffffffu, inc, off);
        if (lane >= off) inc += v;
    }
    int base = inc - pc;
    if (lane < 8) {
        unsigned bits = word; int o = base;
        while (bits) { int b = __ffs(bits) - 1; bits &= bits - 1; nbr[o++] = lane * 32 + b; }
    }
    return __shfl_sync(0xffffffffu, inc, 7);
}

// ---------------------------------------------------------------------------
// K1: blocks [0,128): p_i = (relu(x*W1e[0,i]+b1[0,i]))*w2[0,i]+b2[0,i]
//     4 rows/block, 8-way split-K float4, inline fold.
//     blocks [128,144): edge scatter into g_adj (first consumed by k_ud).
// ---------------------------------------------------------------------------
__global__ void __launch_bounds__(256, 1)
k_p(const int* __restrict__ ei32, int E,
    const float4* __restrict__ x4, const float4* __restrict__ w14,
    const float* __restrict__ b1, const float4* __restrict__ w24,
    const float* __restrict__ b2) {
    int tid = threadIdx.x, lane = tid & 31, w = tid >> 5;
    if (blockIdx.x >= 128) {                  // edge scatter
        // dtype sniff: int64 node ids (<256, nonneg) => odd int32 words zero
        int probe = (2 * tid + 1 < 2 * E) ? ei32[2 * tid + 1] : 0;
        int is64 = __syncthreads_and(probe == 0);
        for (int e = (blockIdx.x - 128) * 256 + tid; e < E; e += 16 * 256) {
            int a, b;
            if (is64) { a = ei32[2 * e]; b = ei32[2 * (E + e)]; }
            else      { a = ei32[e];     b = ei32[E + e]; }
            a &= 255; b &= 255;
            atomicOr(&g_adj[a * 8 + (b >> 5)], 1u << (b & 31));
            atomicOr(&g_adj[b * 8 + (a >> 5)], 1u << (a & 31));
        }
        return;
    }
    int i = blockIdx.x >> 6, row0 = (blockIdx.x & 63) * 4;
    int kb = w * 16;
    __shared__ __align__(16) float S[4][DD];
    __shared__ __align__(16) float H[4][DD];
    __shared__ __align__(16) float red[8][4][DD];

    if (tid < 128) ((float4*)S[tid >> 5])[lane] = x4[(row0 + (tid >> 5)) * 32 + lane];
    __syncthreads();

    {   // L1 GEMM with inline fold
        const float4* W = w14 + i * 8192;     // w1[0,i]
        float4 acc[4] = {};
#pragma unroll
        for (int kk = 0; kk < 16; kk++) {
            int k = kb + kk;
            float4 we = f4add(W[k * 32 + lane], W[(k + 128) * 32 + lane]);
#pragma unroll
            for (int r = 0; r < 4; r++) acc[r] = f4fma(S[r][k], we, acc[r]);
        }
#pragma unroll
        for (int r = 0; r < 4; r++) ((float4*)red[w][r])[lane] = acc[r];
    }
    __syncthreads();
#pragma unroll
    for (int v = 0; v < 2; v++) {             // H = relu(sum + b1[0,i])
        int idx = tid + 256 * v, r = idx >> 7, c = idx & 127;
        float s = b1[i * DD + c];
#pragma unroll
        for (int ww = 0; ww < 8; ww++) s += red[ww][r][c];
        H[r][c] = fmaxf(s, 0.f);
    }
    __syncthreads();
    {   // L2 GEMM
        const float4* W2 = w24 + i * 4096;    // w2[0,i]
        float4 acc[4] = {};
#pragma unroll
        for (int kk = 0; kk < 16; kk++) {
            int k = kb + kk;
            float4 wv = W2[k * 32 + lane];
#pragma unroll
            for (int r = 0; r < 4; r++) acc[r] = f4fma(H[r][k], wv, acc[r]);
        }
#pragma unroll
        for (int r = 0; r < 4; r++) ((float4*)red[w][r])[lane] = acc[r];
    }
    __syncthreads();
    {
        float* dst = i ? g_p1 : g_p0;
#pragma unroll
        for (int v = 0; v < 2; v++) {
            int idx = tid + 256 * v, r = idx >> 7, c = idx & 127;
            float s = b2[i * DD + c];
#pragma unroll
            for (int ww = 0; ww < 8; ww++) s += red[ww][r][c];
            dst[(row0 + r) * DD + c] = s;
        }
    }
}

// ---------------------------------------------------------------------------
// K2: u = x + gather(p0), d = p1-p0; Un_i/Dt_i = {u,d}*W1e[1,i] (inline fold);
// plus corr_i = relu(Un_i+Dt_i+b1[1,i]).w2[1,i]+b2[1,i] (unconditional).
// 128 blocks x 256 thr; i = bid>>6, 4 rows/block.
// ---------------------------------------------------------------------------
__global__ void __launch_bounds__(256, 1)
k_ud(const float4* __restrict__ x4, const float4* __restrict__ w14,
     const float* __restrict__ b1, const float4* __restrict__ w24,
     const float* __restrict__ b2) {
    int tid = threadIdx.x, lane = tid & 31, w = tid >> 5, bid = blockIdx.x;
    int i = bid >> 6, row0 = (bid & 63) * 4;
    int kb = w * 16;
    __shared__ __align__(16) float U[4][DD];          // U then H
    __shared__ __align__(16) float D[4][DD];
    __shared__ __align__(16) float red[8][8][DD];     // 32KB partials
    __shared__ int nbr[4][NN];
    __shared__ int cnts[4];

    // ---- lists (warps 0-3) and d (warps 4-7) ----
    if (w < 4) {
        int cn = build_list(row0 + w, nbr[w]);
        if (lane == 0) cnts[w] = cn;
    } else {
        int row = row0 + (w - 4);
        float4 p1v = ((const float4*)g_p1)[row * 32 + lane];
        float4 p0v = ((const float4*)g_p0)[row * 32 + lane];
        float4 dv = make_float4(p1v.x - p0v.x, p1v.y - p0v.y,
                                p1v.z - p0v.z, p1v.w - p0v.w);
        ((float4*)D[w - 4])[lane] = dv;
        if (i == 0) ((float4*)g_d)[row * 32 + lane] = dv;
    }
    __syncthreads();
    {   // u-gather: warp (r = w&3, half = w>>2) splits list mod 2
        int r = w & 3, half = w >> 2;
        const float4* p04 = (const float4*)g_p0;
        int cn = cnts[r];
        float4 s0 = {}, s1 = {};
        int j = half;
        for (; j + 2 < cn; j += 4) {
            s0 = f4add(s0, p04[nbr[r][j]     * 32 + lane]);
            s1 = f4add(s1, p04[nbr[r][j + 2] * 32 + lane]);
        }
        if (j < cn) s0 = f4add(s0, p04[nbr[r][j] * 32 + lane]);
        ((float4*)red[w][0])[lane] = f4add(s0, s1);   // w = half*4 + r
    }
    __syncthreads();
#pragma unroll
    for (int v = 0; v < 2; v++) {             // U = x + partials
        int idx = tid + 256 * v, r = idx >> 7, c = idx & 127;
        float uv = ((const float*)x4)[(row0 + r) * DD + c]
                 + red[r][0][c] + red[4 + r][0][c];
        U[r][c] = uv;
        if (i == 0) g_u[(row0 + r) * DD + c] = uv;
    }
    __syncthreads();
    {   // GEMM with inline fold: w1[1,i]; U and D share each weight
        const float4* W = w14 + (2 + i) * 8192;
        float4 aU[4] = {}, aD[4] = {};
#pragma unroll
        for (int kk = 0; kk < 16; kk++) {
            int k = kb + kk;
            float4 we = f4add(W[k * 32 + lane], W[(k + 128) * 32 + lane]);
#pragma unroll
            for (int r = 0; r < 4; r++) {
                aU[r] = f4fma(U[r][k], we, aU[r]);
                aD[r] = f4fma(D[r][k], we, aD[r]);
            }
        }
#pragma unroll
        for (int r = 0; r < 4; r++) {
            ((float4*)red[w][r])[lane]     = aU[r];
            ((float4*)red[w][4 + r])[lane] = aD[r];
        }
    }
    __syncthreads();
    {   // reduce 1024 vals; each thread sees Un and Dt for rows t, t+2
        float unv[2], dtv[2];
#pragma unroll
        for (int v = 0; v < 4; v++) {
            int idx = tid + 256 * v;
            int isD = idx >> 9, r = (idx >> 7) & 3, c = idx & 127;
            float s = 0.f;
#pragma unroll
            for (int ww = 0; ww < 8; ww++) s += red[ww][isD * 4 + r][c];
            g_UD[2 * i + isD][(row0 + r) * DD + c] = s;
            int slot = (v & 1);
            if (isD) dtv[slot] = s; else unv[slot] = s;
        }
        __syncthreads();
        int t = tid >> 7, c = tid & 127;
        float b1v = b1[(2 + i) * DD + c];
        U[t][c]     = fmaxf(unv[0] + dtv[0] + b1v, 0.f);   // H rows t, t+2
        U[t + 2][c] = fmaxf(unv[1] + dtv[1] + b1v, 0.f);
    }
    __syncthreads();
    {   // corr GEMM vs w2[1,i]
        const float4* W2 = w24 + (2 + i) * 4096;
        float4 ac[4] = {};
#pragma unroll
        for (int kk = 0; kk < 16; kk++) {
            int k = kb + kk;
            float4 wv = W2[k * 32 + lane];
#pragma unroll
            for (int r = 0; r < 4; r++) ac[r] = f4fma(U[r][k], wv, ac[r]);
        }
#pragma unroll
        for (int r = 0; r < 4; r++) ((float4*)red[w][r])[lane] = ac[r];
    }
    __syncthreads();
#pragma unroll
    for (int v = 0; v < 2; v++) {
        int idx = tid + 256 * v, r = idx >> 7, c = idx & 127;
        float s = b2[(2 + i) * DD + c];
#pragma unroll
        for (int ww = 0; ww < 8; ww++) s += red[ww][r][c];
        g_corr[i][(row0 + r) * DD + c] = s;
    }
}

// ---------------------------------------------------------------------------
// K3: S_t relu-gather + final matvec + epilogue + g_adj restore.
// 128 blocks x 256 thr, 2 rows/block.
// ---------------------------------------------------------------------------
__global__ void __launch_bounds__(256, 1)
k_out(const float* __restrict__ b1, const float4* __restrict__ w24,
      const float* __restrict__ b2, float* __restrict__ out) {
    int tid = threadIdx.x, lane = tid & 31, w = tid >> 5, bid = blockIdx.x;
    int t0 = bid * 2;
    __shared__ __align__(16) float Ssum[2][DD];
    __shared__ __align__(16) float red[8][DD];
    __shared__ int nbr[2][NN];
    __shared__ int cnts[2];

    if (w < 2) {
        int cn = build_list(t0 + w, nbr[w]);
        if (lane == 0) cnts[w] = cn;
    }
    __syncthreads();
    {   // relu-gather: warp (r = w&1, q = w>>1) takes positions q, q+4, ...
        int r = w & 1, q = w >> 1;
        int row = t0 + r;
        const float4* UD0 = (const float4*)g_UD[0];
        float4 pre = f4add(((const float4*)g_UD[1])[row * 32 + lane],
                           ((const float4*)(b1 + 2 * DD))[lane]);
        int cn = cnts[r];
        float4 s0 = {}, s1 = {};
        int j = q;
        for (; j + 4 < cn; j += 8) {
            s0 = f4add(s0, f4relu(f4add(UD0[nbr[r][j]     * 32 + lane], pre)));
            s1 = f4add(s1, f4relu(f4add(UD0[nbr[r][j + 4] * 32 + lane], pre)));
        }
        if (j < cn) s0 = f4add(s0, f4relu(f4add(UD0[nbr[r][j] * 32 + lane], pre)));
        ((float4*)red[w])[lane] = f4add(s0, s1);      // w = q*2 + r
    }
    __syncthreads();
    {   // Ssum reduce: 256 vals / 256 threads
        int r = tid >> 7, c = tid & 127;
        Ssum[r][c] = red[r][c] + red[2 + r][c] + red[4 + r][c] + red[6 + r][c];
    }
    __syncthreads();
    {   // final matvec vs w2[1,0]: warp (r = w&1, q = w>>1), k in [q*32,+32)
        int r = w & 1, q = w >> 1;
        float4 acc = {};
#pragma unroll
        for (int kk = 0; kk < 32; kk++) {
            int k = q * 32 + kk;
            float4 wv = w24[8192 + k * 32 + lane];
            acc = f4fma(Ssum[r][k], wv, acc);
        }
        ((float4*)red[w])[lane] = acc;
    }
    __syncthreads();
    {   // epilogue: thread (r = tid>>7, c)
        int r = tid >> 7, c = tid & 127;
        int t = t0 + r;
        unsigned diag = g_adj[t * 8 + (t >> 5)];
        float sf = (float)((diag >> (t & 31)) & 1);
        float a2 = red[r][c] + red[2 + r][c] + red[4 + r][c] + red[6 + r][c];
        float res = g_u[t * DD + c] + sf * g_d[t * DD + c]
                  + a2 + (float)cnts[r] * b2[2 * DD + c]
                  + sf * (g_corr[1][t * DD + c] - g_corr[0][t * DD + c]);
        out[t * DD + c] = res;
    }
    // restore adjacency rows t0, t0+1 for the next graph replay
    __syncthreads();
    if (tid < 16) g_adj[t0 * 8 + tid] = 0u;
}

extern "C" void kernel_launch(void* const* d_in, const int* in_sizes, int n_in,
                              void* d_out, int out_size) {
    const float* x  = (const float*)d_in[0];
    const float* w1 = (const float*)d_in[1];
    const float* b1 = (const float*)d_in[2];
    const float* w2 = (const float*)d_in[3];
    const float* b2 = (const float*)d_in[4];
    const int*   ei = (const int*)d_in[5];   // dtype sniffed on device
    int E = in_sizes[5] / 2;
    float* out = (float*)d_out;

    k_p  <<<144, 256>>>(ei, E, (const float4*)x, (const float4*)w1,
                        b1, (const float4*)w2, b2);
    k_ud <<<128, 256>>>((const float4*)x, (const float4*)w1,
                        b1, (const float4*)w2, b2);
    k_out<<<128, 256>>>(b1, (const float4*)w2, b2, out);
}